// round 6
// baseline (speedup 1.0000x reference)
#include <cuda_runtime.h>
#include <cstdint>

// ----------------------------------------------------------------------------
// Problem constants
// ----------------------------------------------------------------------------
#define BS_      1024
#define KTOT     33154
#define HID      512
#define ODIM     129
#define ST_LEN   16641
#define AT_LEN_  129
#define ST1_LEN  16384
#define B_AT     16641      /* st | at boundary   */
#define B_ST1    16770      /* at | st1 boundary  */

#define MT       256        /* CTA tile M (batch)  */
#define NT       128        /* CTA tile N (hidden) */
#define CHUNK    64         /* K per stage (fp16)  */
#define NCHUNK   519        /* ceil(33154/64)      */
#define SPLIT    9
#define CPS      58         /* ceil(519/9)         */

#define A_BYTES  (MT * CHUNK * 2)          /* 32768 */
#define B_BYTES  (NT * CHUNK * 2)          /* 16384 */
#define STAGE    (A_BYTES + B_BYTES)       /* 49152 */
#define SMEM_TOTAL (1024 + 2 * STAGE)      /* 99328 */

// split-K partials: 9 * 1024 * 512 * 4 = 18.9 MB
__device__ float g_partial[SPLIT * BS_ * HID];

// ----------------------------------------------------------------------------
// Helpers (plain-sm_103-safe PTX: ldmatrix / mma.sync fp16 / cvt.rn.f16x2)
// ----------------------------------------------------------------------------
__device__ __forceinline__ uint32_t smem_u32(const void* p) {
    uint32_t a;
    asm("{ .reg .u64 t; cvta.to.shared.u64 t, %1; cvt.u32.u64 %0, t; }" : "=r"(a) : "l"(p));
    return a;
}

__device__ __forceinline__ uint32_t swz(uint32_t off) {
    return off ^ ((off >> 3) & 0x70u);
}

// pack two f32 -> f16x2 (lo = x, hi = y), round-to-nearest-even
__device__ __forceinline__ uint32_t pack_f16x2(float x, float y) {
    uint32_t r;
    asm("cvt.rn.f16x2.f32 %0, %1, %2;" : "=r"(r) : "f"(y), "f"(x));
    return r;
}

__device__ __forceinline__ void ldsm_x4(uint32_t r[4], uint32_t addr) {
    asm volatile("ldmatrix.sync.aligned.m8n8.x4.shared.b16 {%0,%1,%2,%3}, [%4];"
                 : "=r"(r[0]), "=r"(r[1]), "=r"(r[2]), "=r"(r[3]) : "r"(addr));
}

__device__ __forceinline__ void ldsm_x2(uint32_t r[2], uint32_t addr) {
    asm volatile("ldmatrix.sync.aligned.m8n8.x2.shared.b16 {%0,%1}, [%2];"
                 : "=r"(r[0]), "=r"(r[1]) : "r"(addr));
}

__device__ __forceinline__ void mma_f16(float c[4], const uint32_t a[4], const uint32_t b[2]) {
    asm volatile(
        "mma.sync.aligned.m16n8k16.row.col.f32.f16.f16.f32 "
        "{%0,%1,%2,%3}, {%4,%5,%6,%7}, {%8,%9}, {%0,%1,%2,%3};"
        : "+f"(c[0]), "+f"(c[1]), "+f"(c[2]), "+f"(c[3])
        : "r"(a[0]), "r"(a[1]), "r"(a[2]), "r"(a[3]), "r"(b[0]), "r"(b[1]));
}

__device__ __forceinline__ void sts32(uint32_t addr, uint32_t v) {
    asm volatile("st.shared.b32 [%0], %1;" :: "r"(addr), "r"(v));
}
__device__ __forceinline__ void sts128(uint32_t addr, uint32_t v0, uint32_t v1, uint32_t v2, uint32_t v3) {
    asm volatile("st.shared.v4.b32 [%0], {%1,%2,%3,%4};" :: "r"(addr), "r"(v0), "r"(v1), "r"(v2), "r"(v3));
}

// ----------------------------------------------------------------------------
// GEMM1: H_partial = X @ W1, fp16 mma.sync m16n8k16, split-K=9.
// grid = 144 CTAs = 4 nt x 4 mt x 9 split, 512 threads (16 warps).
// SMEM per stage: A [256 m][64 k] fp16, B [128 n][64 k] fp16; 128B rows, SW128.
// Warp tile 64(M) x 32(N).
// ----------------------------------------------------------------------------
__global__ void __launch_bounds__(512, 1) gemm1_kernel(
    const float* __restrict__ st, const float* __restrict__ at,
    const float* __restrict__ st1, const float* __restrict__ W1)
{
    extern __shared__ char smem_raw[];
    uint32_t base = smem_u32(smem_raw);
    base = (base + 1023u) & ~1023u;

    const int tid = threadIdx.x;
    const int l   = tid & 31;
    const int w   = tid >> 5;
    const int wm  = w >> 2;       // 0..3
    const int wn  = w & 3;        // 0..3

    const int bx = blockIdx.x;
    const int nt = bx & 3;
    const int mt = (bx >> 2) & 3;
    const int sp = bx >> 4;       // 0..8

    const int c0  = sp * CPS;
    int nch = NCHUNK - c0;
    if (nch > CPS) nch = CPS;

    // A staging geometry: kp = tid&31 -> k pair (2*kp, 2*kp+1), rg = tid>>5 -> 16 rows
    const int kp = tid & 31;
    const int rg = tid >> 5;
    const int am_base = mt * MT + rg * 16;

    // B staging geometry: n = tid&127, kg = tid>>7 -> 16 k values
    const int bn  = tid & 127;
    const int bkg = tid >> 7;                 // 0..3
    const float* W1p = W1 + (size_t)(nt * NT + bn);

    // scalar X element
    auto loadX = [&](int m, int k) -> float {
        if (k < B_AT)   return __ldg(st  + (size_t)m * ST_LEN  + k);
        if (k < B_ST1)  return __ldg(at  + (size_t)m * AT_LEN_ + (k - B_AT));
        if (k < KTOT)   return __ldg(st1 + (size_t)m * ST1_LEN + (k - B_ST1));
        return 0.0f;
    };

    // load 8 rows (half of this thread's 16) of the k pair
    auto loadA = [&](int chunk, int half, float2 v[8]) {
        const int k = chunk * CHUNK + 2 * kp;
        const int m0 = am_base + half * 8;
#pragma unroll
        for (int r = 0; r < 8; ++r) {
            v[r].x = loadX(m0 + r, k);
            v[r].y = loadX(m0 + r, k + 1);
        }
    };
    auto storeA = [&](int s, int half, const float2 v[8]) {
        const uint32_t Ab = base + (uint32_t)s * STAGE;
#pragma unroll
        for (int r = 0; r < 8; ++r)
            sts32(Ab + swz((uint32_t)((rg * 16 + half * 8 + r) * 128 + kp * 4)),
                  pack_f16x2(v[r].x, v[r].y));
    };

    // B: 16 k values of column bn (transpose W1[k][n] -> smem[n][k])
    auto loadB = [&](int chunk, float bF[16]) {
        const int kb = chunk * CHUNK + bkg * 16;
#pragma unroll
        for (int j = 0; j < 16; ++j) {
            const int k = kb + j;
            bF[j] = (k < KTOT) ? __ldg(W1p + (size_t)k * HID) : 0.0f;
        }
    };
    auto storeB = [&](int s, const float bF[16]) {
        const uint32_t Bb = base + (uint32_t)s * STAGE + A_BYTES;
        uint32_t p0 = pack_f16x2(bF[0], bF[1]),  p1 = pack_f16x2(bF[2], bF[3]);
        uint32_t p2 = pack_f16x2(bF[4], bF[5]),  p3 = pack_f16x2(bF[6], bF[7]);
        sts128(Bb + swz((uint32_t)(bn * 128 + bkg * 32)), p0, p1, p2, p3);
        p0 = pack_f16x2(bF[8], bF[9]);   p1 = pack_f16x2(bF[10], bF[11]);
        p2 = pack_f16x2(bF[12], bF[13]); p3 = pack_f16x2(bF[14], bF[15]);
        sts128(Bb + swz((uint32_t)(bn * 128 + bkg * 32 + 16)), p0, p1, p2, p3);
    };

    // ---- fragment smem offsets (pre-swizzle, in-tile) ----
    uint32_t relA[4], relB[4];
#pragma unroll
    for (int t = 0; t < 4; ++t)
        relA[t] = (uint32_t)((wm * 64 + t * 16 + (l & 7) + ((l >> 3) & 1) * 8) * 128
                             + ((l >> 4) & 1) * 16);
    const int lm = l & 15;
#pragma unroll
    for (int u = 0; u < 4; ++u)
        relB[u] = (uint32_t)((wn * 32 + u * 8 + (lm & 7)) * 128 + ((lm >> 3) & 1) * 16);

    float acc[4][4][4];
#pragma unroll
    for (int t = 0; t < 4; ++t)
#pragma unroll
        for (int u = 0; u < 4; ++u)
#pragma unroll
            for (int j = 0; j < 4; ++j) acc[t][u][j] = 0.0f;

    // ---- prologue ----
    {
        float2 v[8]; float bF[16];
        loadA(c0, 0, v); storeA(0, 0, v);
        loadA(c0, 1, v); storeA(0, 1, v);
        loadB(c0, bF);   storeB(0, bF);
    }
    __syncthreads();

    // ---- main loop ----
    for (int i = 0; i < nch; ++i) {
        const int s = i & 1;
        const uint32_t Ab = base + (uint32_t)s * STAGE;
        const uint32_t Bb = Ab + A_BYTES;
        const bool pf = (i + 1 < nch);

        // one K=16 step
        auto compute_ks = [&](int ks) {
            uint32_t afr[4][4], bfr[4][2];
#pragma unroll
            for (int t = 0; t < 4; ++t) ldsm_x4(afr[t], Ab + swz(relA[t] + ks * 32));
#pragma unroll
            for (int u = 0; u < 4; ++u) ldsm_x2(bfr[u], Bb + swz(relB[u] + ks * 32));
#pragma unroll
            for (int t = 0; t < 4; ++t)
#pragma unroll
                for (int u = 0; u < 4; ++u)
                    mma_f16(acc[t][u], afr[t], bfr[u]);
        };

        {
            float2 v[8];
            if (pf) loadA(c0 + i + 1, 0, v);
            compute_ks(0);
            if (pf) storeA(s ^ 1, 0, v);
        }
        {
            float2 v[8];
            if (pf) loadA(c0 + i + 1, 1, v);
            compute_ks(1);
            if (pf) storeA(s ^ 1, 1, v);
        }
        {
            float bF[16];
            if (pf) loadB(c0 + i + 1, bF);
            compute_ks(2);
            if (pf) storeB(s ^ 1, bF);
        }
        compute_ks(3);
        __syncthreads();
    }

    // ---- epilogue: write split-K partials ----
    float* outp = g_partial + (size_t)sp * BS_ * HID;
#pragma unroll
    for (int t = 0; t < 4; ++t) {
        const int row0 = mt * MT + wm * 64 + t * 16 + (l >> 2);
#pragma unroll
        for (int u = 0; u < 4; ++u) {
            const int col = nt * NT + wn * 32 + u * 8 + (l & 3) * 2;
            float2 v0; v0.x = acc[t][u][0]; v0.y = acc[t][u][1];
            float2 v1; v1.x = acc[t][u][2]; v1.y = acc[t][u][3];
            *(float2*)(outp + (size_t)row0 * HID + col)       = v0;
            *(float2*)(outp + (size_t)(row0 + 8) * HID + col) = v1;
        }
    }
}

// ----------------------------------------------------------------------------
// Kernel 2: reduce split-K partials + b1 + ReLU, then H @ W2 + b2.
// grid = 256 CTAs x 512 threads; 4 batch rows per CTA.
// Phase 1: one float4 9-way reduce per thread (all loads independent).
// Phase 2: 516 dot products over 512 threads, W2 accessed coalesced in j.
// ----------------------------------------------------------------------------
__global__ void __launch_bounds__(512) mlp2_kernel(
    const float* __restrict__ b1, const float* __restrict__ W2,
    const float* __restrict__ b2, float* __restrict__ out)
{
    __shared__ float h_s[4 * HID];   // 8 KB
    const int tid = threadIdx.x;
    const int row0 = blockIdx.x * 4;

    // Phase 1: 4 rows x 128 float4 = 512 float4 -> exactly 1 per thread
    {
        const int r  = tid >> 7;        // 0..3
        const int c4 = tid & 127;       // float4 column
        float4 s = __ldg((const float4*)b1 + c4);
#pragma unroll
        for (int sp = 0; sp < SPLIT; ++sp) {
            float4 p = *((const float4*)g_partial +
                         ((size_t)sp * BS_ + (row0 + r)) * (HID / 4) + c4);
            s.x += p.x; s.y += p.y; s.z += p.z; s.w += p.w;
        }
        float4* dst = (float4*)h_s + r * (HID / 4) + c4;
        dst->x = fmaxf(s.x, 0.0f); dst->y = fmaxf(s.y, 0.0f);
        dst->z = fmaxf(s.z, 0.0f); dst->w = fmaxf(s.w, 0.0f);
    }
    __syncthreads();

    // Phase 2: 4*129 = 516 dots; thread handles d = tid (+512 for tid<4)
    for (int d = tid; d < 4 * ODIM; d += 512) {
        const int r = d / ODIM;
        const int j = d - r * ODIM;
        const float* hrow = h_s + r * HID;
        const float* w2p  = W2 + j;
        float a0 = 0.f, a1 = 0.f, a2 = 0.f, a3 = 0.f;
#pragma unroll 4
        for (int k = 0; k < HID; k += 4) {
            a0 = fmaf(hrow[k + 0], __ldg(w2p + (size_t)(k + 0) * ODIM), a0);
            a1 = fmaf(hrow[k + 1], __ldg(w2p + (size_t)(k + 1) * ODIM), a1);
            a2 = fmaf(hrow[k + 2], __ldg(w2p + (size_t)(k + 2) * ODIM), a2);
            a3 = fmaf(hrow[k + 3], __ldg(w2p + (size_t)(k + 3) * ODIM), a3);
        }
        out[(size_t)row0 * ODIM + d] = (a0 + a1) + (a2 + a3) + __ldg(b2 + j);
    }
}

// ----------------------------------------------------------------------------
// Launch
// ----------------------------------------------------------------------------
extern "C" void kernel_launch(void* const* d_in, const int* in_sizes, int n_in,
                              void* d_out, int out_size) {
    const float* st  = (const float*)d_in[0];
    const float* at  = (const float*)d_in[1];
    const float* st1 = (const float*)d_in[2];
    const float* W1  = (const float*)d_in[3];
    const float* b1  = (const float*)d_in[4];
    const float* W2  = (const float*)d_in[5];
    const float* b2  = (const float*)d_in[6];
    float* out = (float*)d_out;

    cudaFuncSetAttribute(gemm1_kernel, cudaFuncAttributeMaxDynamicSharedMemorySize, SMEM_TOTAL);

    gemm1_kernel<<<144, 512, SMEM_TOTAL>>>(st, at, st1, W1);
    mlp2_kernel<<<BS_ / 4, 512>>>(b1, W2, b2, out);
}